// round 1
// baseline (speedup 1.0000x reference)
#include <cuda_runtime.h>
#include <cuda_bf16.h>

// Problem constants (B=1, L=1024, TOKEN_Z=128, R_MAX=32, S_MAX=2)
#define LSEQ   1024
#define TZ     128          // channels
#define TZ4    32           // channels as float4
#define N_REL  66           // 2*R_MAX + 2
#define N_CH   6            // 2*S_MAX + 2
#define N_ROWS 139          // 66 + 66 + 1 + 6
// W layout rows: [0,66) = W_pos, [66,132) = W_tok, 132 = w_ent, [133,139) = W_ch

// Shared memory layout (bytes):
//   sW    : N_ROWS * 32 float4 = 71168
//   sBase : 32 float4          = 512    (W_pos[65] + W_tok[65])
//   6 int arrays of 1024       = 24576
// total = 96256 bytes  -> needs dynamic smem attribute (>48KB)
#define SMEM_BYTES (N_ROWS * TZ4 * 16 + TZ4 * 16 + 6 * LSEQ * 4)

__device__ __forceinline__ float4 f4add(float4 a, float4 b) {
    return make_float4(a.x + b.x, a.y + b.y, a.z + b.z, a.w + b.w);
}

__global__ __launch_bounds__(256, 2)
void relpos_kernel(const int* __restrict__ asym,
                   const int* __restrict__ resi,
                   const int* __restrict__ ent,
                   const int* __restrict__ tok,
                   const int* __restrict__ sym,
                   const int* __restrict__ cyc,
                   const float* __restrict__ W,
                   float* __restrict__ out)
{
    extern __shared__ char smem_raw[];
    float4* sW    = reinterpret_cast<float4*>(smem_raw);
    float4* sBase = sW + N_ROWS * TZ4;
    int* sAsym = reinterpret_cast<int*>(sBase + TZ4);
    int* sResi = sAsym + LSEQ;
    int* sEnt  = sResi + LSEQ;
    int* sTok  = sEnt  + LSEQ;
    int* sSym  = sTok  + LSEQ;
    int* sCyc  = sSym  + LSEQ;

    const int tid = threadIdx.x;

    // Stage W (vectorized) and the six index arrays into smem.
    const float4* W4 = reinterpret_cast<const float4*>(W);
    #pragma unroll 4
    for (int k = tid; k < N_ROWS * TZ4; k += 256) sW[k] = W4[k];
    for (int k = tid; k < LSEQ; k += 256) {
        sAsym[k] = asym[k];
        sResi[k] = resi[k];
        sEnt[k]  = ent[k];
        sTok[k]  = tok[k];
        sSym[k]  = sym[k];
        sCyc[k]  = cyc[k];
    }
    __syncthreads();

    const int lane = tid & 31;
    // Precompute the "different chain" base row: W_pos[65] + W_tok[65]
    if (tid < 32) {
        sBase[lane] = f4add(sW[65 * TZ4 + lane], sW[(66 + 65) * TZ4 + lane]);
    }
    __syncthreads();

    const int i = blockIdx.x;
    const int ai = sAsym[i];
    const int ri = sResi[i];
    const int ei = sEnt[i];
    const int ti = sTok[i];
    const int si = sSym[i];

    // Register-resident rows for this lane's float4 slice.
    const float4 went = sW[132 * TZ4 + lane];          // w_ent
    const float4 wch5 = sW[(133 + 5) * TZ4 + lane];    // W_ch[5] (same-chain case)
    const float4 base = sBase[lane];                   // Wpos[65]+Wtok[65] (diff-chain case)

    const int warp = tid >> 5;
    float4* out4 = reinterpret_cast<float4*>(out) + (size_t)i * LSEQ * TZ4;

    for (int j = warp; j < LSEQ; j += 8) {
        const int aj = sAsym[j];
        const bool same_chain  = (ai == aj);
        const bool same_entity = (ei == sEnt[j]);

        float4 r;
        if (same_chain) {
            const int rj  = sResi[j];
            int rel = ri - rj;
            const int cj = sCyc[j];
            const int period = (cj > 0) ? cj : 10000;
            // rel -= (period * round(rel/period))  (round half-to-even, trunc-to-int cast)
            const float q = rintf((float)rel / (float)period);
            rel -= (int)((float)period * q);
            const int dr = min(max(rel + 32, 0), 64);
            int dt = 65;
            if (ri == rj) dt = min(max(ti - sTok[j] + 32, 0), 64);
            const float4 a = sW[dr * TZ4 + lane];
            const float4 b = sW[(66 + dt) * TZ4 + lane];
            // same chain => d_chain = 2*S_MAX+1 = 5 (register row)
            r = f4add(f4add(a, b), wch5);
        } else {
            // diff chain => d_residue=65, d_token=65 (precombined base row)
            const int dc = min(max(si - sSym[j] + 2, 0), 4);
            const float4 c = sW[(133 + dc) * TZ4 + lane];
            r = f4add(base, c);
        }
        if (same_entity) r = f4add(r, went);

        out4[(size_t)j * TZ4 + lane] = r;
    }
}

extern "C" void kernel_launch(void* const* d_in, const int* in_sizes, int n_in,
                              void* d_out, int out_size) {
    const int*   asym = (const int*)d_in[0];
    const int*   resi = (const int*)d_in[1];
    const int*   ent  = (const int*)d_in[2];
    const int*   tok  = (const int*)d_in[3];
    const int*   sym  = (const int*)d_in[4];
    const int*   cyc  = (const int*)d_in[5];
    const float* W    = (const float*)d_in[6];
    float* out = (float*)d_out;

    cudaFuncSetAttribute(relpos_kernel,
                         cudaFuncAttributeMaxDynamicSharedMemorySize, SMEM_BYTES);

    relpos_kernel<<<LSEQ, 256, SMEM_BYTES>>>(asym, resi, ent, tok, sym, cyc, W, out);
}

// round 2
// speedup vs baseline: 1.0003x; 1.0003x over previous
#include <cuda_runtime.h>
#include <cuda_bf16.h>

// Problem constants (B=1, L=1024, TOKEN_Z=128, R_MAX=32, S_MAX=2)
#define LSEQ   1024
#define TZ4    32           // 128 channels as float4
// W rows: [0,66)=W_pos, [66,132)=W_tok, 132=w_ent, [133,139)=W_ch
// Combined tables:
//   A[67]: A[k]=W_pos[k]+W_ch[5] for k<66 ; A[66]=W_pos[65]+W_tok[65]
//   B[72]: B[k]=W_tok[k] for k<66 ; B[66+c]=W_ch[c]
#define NA 67
#define NB 72
// smem: (67+72)*32 float4 + 1024 descriptors = 71168 + 4096 = 75264 bytes
#define SMEM_BYTES ((NA + NB) * TZ4 * 16 + LSEQ * 4)

__device__ __forceinline__ float4 f4add(float4 a, float4 b) {
    return make_float4(a.x + b.x, a.y + b.y, a.z + b.z, a.w + b.w);
}

__global__ __launch_bounds__(256, 3)
void relpos_kernel(const int* __restrict__ asym,
                   const int* __restrict__ resi,
                   const int* __restrict__ ent,
                   const int* __restrict__ tok,
                   const int* __restrict__ sym,
                   const int* __restrict__ cyc,
                   const float* __restrict__ W,
                   float* __restrict__ out)
{
    extern __shared__ char smem_raw[];
    float4* sA    = reinterpret_cast<float4*>(smem_raw);
    float4* sB    = sA + NA * TZ4;
    int*    sDesc = reinterpret_cast<int*>(sB + NB * TZ4);

    const int tid  = threadIdx.x;
    const int lane = tid & 31;
    const int i    = blockIdx.x;

    const float4* W4 = reinterpret_cast<const float4*>(W);

    // ---- Build combined table A (67 rows) ----
    // A[k<66] = W_pos[k] + W_ch[5];  A[66] = W_pos[65] + W_tok[65]
    #pragma unroll 2
    for (int k = tid; k < NA * TZ4; k += 256) {
        const int row = k >> 5, ln = k & 31;
        float4 v;
        if (row < 66) {
            v = f4add(__ldg(&W4[row * TZ4 + ln]), __ldg(&W4[(133 + 5) * TZ4 + ln]));
        } else {
            v = f4add(__ldg(&W4[65 * TZ4 + ln]), __ldg(&W4[(66 + 65) * TZ4 + ln]));
        }
        sA[k] = v;
    }
    // ---- Build table B (72 rows): W_tok rows then W_ch rows ----
    #pragma unroll 2
    for (int k = tid; k < NB * TZ4; k += 256) {
        const int row = k >> 5, ln = k & 31;
        const int src = (row < 66) ? (66 + row) : (133 + (row - 66));
        sB[k] = __ldg(&W4[src * TZ4 + ln]);
    }

    // ---- Per-block scalars (warp-uniform global loads, L2-hot) ----
    const int ai = __ldg(&asym[i]);
    const int ri = __ldg(&resi[i]);
    const int ei = __ldg(&ent[i]);
    const int ti = __ldg(&tok[i]);
    const int si = __ldg(&sym[i]);

    // ---- Precompute per-j descriptors: idxA | idxB<<8 | ent<<16 ----
    #pragma unroll 4
    for (int j = tid; j < LSEQ; j += 256) {
        const int aj = __ldg(&asym[j]);
        int idxA, idxB;
        if (ai == aj) {
            const int rj = __ldg(&resi[j]);
            int rel = ri - rj;
            const int cj = __ldg(&cyc[j]);
            const int period = (cj > 0) ? cj : 10000;
            const float q = rintf((float)rel / (float)period);
            rel -= (int)((float)period * q);
            idxA = min(max(rel + 32, 0), 64);                 // d_residue
            idxB = 65;
            if (ri == rj) idxB = min(max(ti - __ldg(&tok[j]) + 32, 0), 64);  // d_token
        } else {
            idxA = 66;                                        // combined diff-chain base
            idxB = 66 + min(max(si - __ldg(&sym[j]) + 2, 0), 4);
        }
        const int e = (ei == __ldg(&ent[j])) ? 1 : 0;
        sDesc[j] = idxA | (idxB << 8) | (e << 16);
    }
    __syncthreads();

    // ---- Register-resident w_ent slice for this lane ----
    const float4 went = __ldg(&W4[132 * TZ4 + lane]);

    const int warp = tid >> 5;
    float4* out4 = reinterpret_cast<float4*>(out) + (size_t)i * LSEQ * TZ4;

    // Each warp handles j = warp + 8*k ; unroll by 4 for MLP.
    for (int jj = warp; jj < LSEQ; jj += 32) {
        const int j0 = jj, j1 = jj + 8, j2 = jj + 16, j3 = jj + 24;
        const int d0 = sDesc[j0];
        const int d1 = sDesc[j1];
        const int d2 = sDesc[j2];
        const int d3 = sDesc[j3];

        const float4 a0 = sA[(d0 & 0xFF) * TZ4 + lane];
        const float4 b0 = sB[((d0 >> 8) & 0xFF) * TZ4 + lane];
        const float4 a1 = sA[(d1 & 0xFF) * TZ4 + lane];
        const float4 b1 = sB[((d1 >> 8) & 0xFF) * TZ4 + lane];
        const float4 a2 = sA[(d2 & 0xFF) * TZ4 + lane];
        const float4 b2 = sB[((d2 >> 8) & 0xFF) * TZ4 + lane];
        const float4 a3 = sA[(d3 & 0xFF) * TZ4 + lane];
        const float4 b3 = sB[((d3 >> 8) & 0xFF) * TZ4 + lane];

        float4 r0 = f4add(a0, b0);
        float4 r1 = f4add(a1, b1);
        float4 r2 = f4add(a2, b2);
        float4 r3 = f4add(a3, b3);
        if (d0 & 0x10000) r0 = f4add(r0, went);
        if (d1 & 0x10000) r1 = f4add(r1, went);
        if (d2 & 0x10000) r2 = f4add(r2, went);
        if (d3 & 0x10000) r3 = f4add(r3, went);

        out4[(size_t)j0 * TZ4 + lane] = r0;
        out4[(size_t)j1 * TZ4 + lane] = r1;
        out4[(size_t)j2 * TZ4 + lane] = r2;
        out4[(size_t)j3 * TZ4 + lane] = r3;
    }
}

extern "C" void kernel_launch(void* const* d_in, const int* in_sizes, int n_in,
                              void* d_out, int out_size) {
    const int*   asym = (const int*)d_in[0];
    const int*   resi = (const int*)d_in[1];
    const int*   entp = (const int*)d_in[2];
    const int*   tokp = (const int*)d_in[3];
    const int*   symp = (const int*)d_in[4];
    const int*   cycp = (const int*)d_in[5];
    const float* W    = (const float*)d_in[6];
    float* out = (float*)d_out;

    cudaFuncSetAttribute(relpos_kernel,
                         cudaFuncAttributeMaxDynamicSharedMemorySize, SMEM_BYTES);

    relpos_kernel<<<LSEQ, 256, SMEM_BYTES>>>(asym, resi, entp, tokp, symp, cycp, W, out);
}

// round 3
// speedup vs baseline: 1.1801x; 1.1798x over previous
#include <cuda_runtime.h>
#include <cuda_bf16.h>

// Problem constants (B=1, L=1024, TOKEN_Z=128, R_MAX=32, S_MAX=2)
#define LSEQ   1024
#define JHALF  512          // each block handles half a row
#define TZ4    32           // 128 channels as float4
// W rows: [0,66)=W_pos, [66,132)=W_tok, 132=w_ent, [133,139)=W_ch
// Combined tables:
//   A[67]: A[k]=W_pos[k]+W_ch[5] for k<66 ; A[66]=W_pos[65]+W_tok[65]
//   B[72]: B[k]=W_tok[k] for k<66 ; B[66+c]=W_ch[c]
#define NA 67
#define NB 72
// smem: (67+72)*32 float4 + 512 descriptors = 71168 + 2048 = 73216 bytes -> 3 CTAs/SM
#define SMEM_BYTES ((NA + NB) * TZ4 * 16 + JHALF * 4)

__device__ __forceinline__ float4 f4add(float4 a, float4 b) {
    return make_float4(a.x + b.x, a.y + b.y, a.z + b.z, a.w + b.w);
}

__global__ __launch_bounds__(256, 3)
void relpos_kernel(const int* __restrict__ asym,
                   const int* __restrict__ resi,
                   const int* __restrict__ ent,
                   const int* __restrict__ tok,
                   const int* __restrict__ sym,
                   const int* __restrict__ cyc,
                   const float* __restrict__ W,
                   float* __restrict__ out)
{
    extern __shared__ char smem_raw[];
    float4* sA    = reinterpret_cast<float4*>(smem_raw);
    float4* sB    = sA + NA * TZ4;
    int*    sDesc = reinterpret_cast<int*>(sB + NB * TZ4);

    const int tid  = threadIdx.x;
    const int lane = tid & 31;
    const int i     = blockIdx.x >> 1;          // row
    const int jbase = (blockIdx.x & 1) * JHALF; // half-row offset

    const float4* W4 = reinterpret_cast<const float4*>(W);

    // ---- Build combined table A (67 rows) ----
    #pragma unroll 2
    for (int k = tid; k < NA * TZ4; k += 256) {
        const int row = k >> 5, ln = k & 31;
        float4 v;
        if (row < 66) {
            v = f4add(__ldg(&W4[row * TZ4 + ln]), __ldg(&W4[(133 + 5) * TZ4 + ln]));
        } else {
            v = f4add(__ldg(&W4[65 * TZ4 + ln]), __ldg(&W4[(66 + 65) * TZ4 + ln]));
        }
        sA[k] = v;
    }
    // ---- Build table B (72 rows): W_tok rows then W_ch rows ----
    #pragma unroll 2
    for (int k = tid; k < NB * TZ4; k += 256) {
        const int row = k >> 5, ln = k & 31;
        const int src = (row < 66) ? (66 + row) : (133 + (row - 66));
        sB[k] = __ldg(&W4[src * TZ4 + ln]);
    }

    // ---- Per-block scalars ----
    const int ai = __ldg(&asym[i]);
    const int ri = __ldg(&resi[i]);
    const int ei = __ldg(&ent[i]);
    const int ti = __ldg(&tok[i]);
    const int si = __ldg(&sym[i]);

    // ---- Precompute descriptors for this half-row: idxA | idxB<<8 | ent<<16 ----
    #pragma unroll 2
    for (int jj = tid; jj < JHALF; jj += 256) {
        const int j = jbase + jj;
        const int aj = __ldg(&asym[j]);
        int idxA, idxB;
        if (ai == aj) {
            const int rj = __ldg(&resi[j]);
            int rel = ri - rj;
            const int cj = __ldg(&cyc[j]);
            const int period = (cj > 0) ? cj : 10000;
            const float q = rintf((float)rel / (float)period);
            rel -= (int)((float)period * q);
            idxA = min(max(rel + 32, 0), 64);                 // d_residue
            idxB = 65;
            if (ri == rj) idxB = min(max(ti - __ldg(&tok[j]) + 32, 0), 64);  // d_token
        } else {
            idxA = 66;                                        // combined diff-chain base
            idxB = 66 + min(max(si - __ldg(&sym[j]) + 2, 0), 4);
        }
        const int e = (ei == __ldg(&ent[j])) ? 1 : 0;
        sDesc[jj] = idxA | (idxB << 8) | (e << 16);
    }
    __syncthreads();

    const float4 went = __ldg(&W4[132 * TZ4 + lane]);

    const int warp = tid >> 5;
    // Warp handles 4 CONSECUTIVE j's per iteration -> 2KB contiguous store span.
    float4* out4 = reinterpret_cast<float4*>(out)
                 + (size_t)i * LSEQ * TZ4 + (size_t)jbase * TZ4;
    const int4* sDesc4 = reinterpret_cast<const int4*>(sDesc);

    #pragma unroll 4
    for (int k = 0; k < 16; k++) {
        const int u  = warp + k * 8;       // int4 index: j0 = 4*u
        const int4 d = sDesc4[u];          // broadcast LDS.128 (4 descriptors)

        const float4 a0 = sA[(d.x & 0xFF) * TZ4 + lane];
        const float4 b0 = sB[((d.x >> 8) & 0xFF) * TZ4 + lane];
        const float4 a1 = sA[(d.y & 0xFF) * TZ4 + lane];
        const float4 b1 = sB[((d.y >> 8) & 0xFF) * TZ4 + lane];
        const float4 a2 = sA[(d.z & 0xFF) * TZ4 + lane];
        const float4 b2 = sB[((d.z >> 8) & 0xFF) * TZ4 + lane];
        const float4 a3 = sA[(d.w & 0xFF) * TZ4 + lane];
        const float4 b3 = sB[((d.w >> 8) & 0xFF) * TZ4 + lane];

        float4 r0 = f4add(a0, b0);
        float4 r1 = f4add(a1, b1);
        float4 r2 = f4add(a2, b2);
        float4 r3 = f4add(a3, b3);
        if (d.x & 0x10000) r0 = f4add(r0, went);
        if (d.y & 0x10000) r1 = f4add(r1, went);
        if (d.z & 0x10000) r2 = f4add(r2, went);
        if (d.w & 0x10000) r3 = f4add(r3, went);

        float4* p = out4 + (size_t)(4 * u) * TZ4 + lane;
        __stcs(p,           r0);
        __stcs(p + TZ4,     r1);
        __stcs(p + 2 * TZ4, r2);
        __stcs(p + 3 * TZ4, r3);
    }
}

extern "C" void kernel_launch(void* const* d_in, const int* in_sizes, int n_in,
                              void* d_out, int out_size) {
    const int*   asym = (const int*)d_in[0];
    const int*   resi = (const int*)d_in[1];
    const int*   entp = (const int*)d_in[2];
    const int*   tokp = (const int*)d_in[3];
    const int*   symp = (const int*)d_in[4];
    const int*   cycp = (const int*)d_in[5];
    const float* W    = (const float*)d_in[6];
    float* out = (float*)d_out;

    cudaFuncSetAttribute(relpos_kernel,
                         cudaFuncAttributeMaxDynamicSharedMemorySize, SMEM_BYTES);

    relpos_kernel<<<2 * LSEQ, 256, SMEM_BYTES>>>(asym, resi, entp, tokp, symp, cycp, W, out);
}

// round 4
// speedup vs baseline: 1.2299x; 1.0422x over previous
#include <cuda_runtime.h>
#include <cuda_bf16.h>

// Problem constants (B=1, L=1024, TOKEN_Z=128, R_MAX=32, S_MAX=2)
#define LSEQ   1024
#define JHALF  512          // each block handles half a row
#define TZ4    32           // 128 channels as float4
// W rows: [0,66)=W_pos, [66,132)=W_tok, 132=w_ent, [133,139)=W_ch
//
// Unified folded table T (136 rows of 32 float4):
//   T[0..64]   = D[dr] = W_pos[dr] + W_tok[65] + W_ch[5]   (same-chain, dt=65)
//   T[65..69]  = C[dc] = W_pos[65] + W_tok[65] + W_ch[dc]  (diff-chain)
//   T[70..135] = W_tok[0..65]                              (rare same-residue fixup)
#define NT 136
// smem: 136*32 float4 + 512 descriptors = 69632 + 2048 = 71680 bytes -> 3 CTAs/SM
#define SMEM_BYTES (NT * TZ4 * 16 + JHALF * 4)

__device__ __forceinline__ float4 f4add(float4 a, float4 b) {
    return make_float4(a.x + b.x, a.y + b.y, a.z + b.z, a.w + b.w);
}

__global__ __launch_bounds__(256, 3)
void relpos_kernel(const int* __restrict__ asym,
                   const int* __restrict__ resi,
                   const int* __restrict__ ent,
                   const int* __restrict__ tok,
                   const int* __restrict__ sym,
                   const int* __restrict__ cyc,
                   const float* __restrict__ W,
                   float* __restrict__ out)
{
    extern __shared__ char smem_raw[];
    float4* sT    = reinterpret_cast<float4*>(smem_raw);
    int*    sDesc = reinterpret_cast<int*>(sT + NT * TZ4);

    const int tid  = threadIdx.x;
    const int lane = tid & 31;
    const int i     = blockIdx.x >> 1;          // row
    const int jbase = (blockIdx.x & 1) * JHALF; // half-row offset

    const float4* W4 = reinterpret_cast<const float4*>(W);

    // ---- Build folded table: each thread owns a fixed lane, strides rows ----
    {
        const float4 wtok65 = __ldg(&W4[(66 + 65) * TZ4 + lane]);
        const float4 wch5   = __ldg(&W4[(133 + 5) * TZ4 + lane]);
        const float4 base65 = f4add(__ldg(&W4[65 * TZ4 + lane]), wtok65); // Wpos65+Wtok65
        const int row0 = tid >> 5;   // 0..7
        #pragma unroll
        for (int r = row0; r < NT; r += 8) {
            float4 v;
            if (r < 65) {
                v = f4add(f4add(__ldg(&W4[r * TZ4 + lane]), wtok65), wch5);
            } else if (r < 70) {
                v = f4add(base65, __ldg(&W4[(133 + (r - 65)) * TZ4 + lane]));
            } else {
                v = __ldg(&W4[(66 + (r - 70)) * TZ4 + lane]);
            }
            sT[r * TZ4 + lane] = v;
        }
    }

    // ---- Per-block scalars ----
    const int ai = __ldg(&asym[i]);
    const int ri = __ldg(&resi[i]);
    const int ei = __ldg(&ent[i]);
    const int ti = __ldg(&tok[i]);
    const int si = __ldg(&sym[i]);

    // ---- Descriptors: idxT | idxB<<8 (0xFF = none) | e<<16 ----
    #pragma unroll 2
    for (int jj = tid; jj < JHALF; jj += 256) {
        const int j = jbase + jj;
        const int aj = __ldg(&asym[j]);
        int idxT, idxB = 0xFF;
        if (ai == aj) {
            const int rj = __ldg(&resi[j]);
            int rel = ri - rj;
            const int cj = __ldg(&cyc[j]);
            const int period = (cj > 0) ? cj : 10000;
            const float q = rintf((float)rel / (float)period);
            rel -= (int)((float)period * q);
            idxT = min(max(rel + 32, 0), 64);                 // d_residue -> D row
            if (ri == rj)                                     // rare: needs W_tok fixup
                idxB = min(max(ti - __ldg(&tok[j]) + 32, 0), 64);
        } else {
            idxT = 65 + min(max(si - __ldg(&sym[j]) + 2, 0), 4); // C row
        }
        const int e = (ei == __ldg(&ent[j])) ? 1 : 0;
        sDesc[jj] = idxT | (idxB << 8) | (e << 16);
    }
    __syncthreads();

    // ---- Register-resident lane slices ----
    const float4 went  = __ldg(&W4[132 * TZ4 + lane]);
    const float4 wt65  = __ldg(&W4[(66 + 65) * TZ4 + lane]);
    const float4 nwt65 = make_float4(-wt65.x, -wt65.y, -wt65.z, -wt65.w);

    const int warp = tid >> 5;
    float4* out4 = reinterpret_cast<float4*>(out)
                 + (size_t)i * LSEQ * TZ4 + (size_t)jbase * TZ4;
    const int4* sDesc4 = reinterpret_cast<const int4*>(sDesc);

    #pragma unroll 4
    for (int k = 0; k < 16; k++) {
        const int u  = warp + k * 8;       // int4 index: j0 = 4*u
        const int4 d = sDesc4[u];          // broadcast LDS.128 (4 descriptors)

        float4 r0 = sT[(d.x & 0xFF) * TZ4 + lane];
        float4 r1 = sT[(d.y & 0xFF) * TZ4 + lane];
        float4 r2 = sT[(d.z & 0xFF) * TZ4 + lane];
        float4 r3 = sT[(d.w & 0xFF) * TZ4 + lane];

        if (d.x & 0x10000) r0 = f4add(r0, went);
        if (d.y & 0x10000) r1 = f4add(r1, went);
        if (d.z & 0x10000) r2 = f4add(r2, went);
        if (d.w & 0x10000) r3 = f4add(r3, went);

        // Rare same-residue fixup: + W_tok[dt] - W_tok[65]  (warp-uniform branches)
        const int b0 = (d.x >> 8) & 0xFF;
        const int b1 = (d.y >> 8) & 0xFF;
        const int b2 = (d.z >> 8) & 0xFF;
        const int b3 = (d.w >> 8) & 0xFF;
        if (b0 != 0xFF) r0 = f4add(r0, f4add(sT[(70 + b0) * TZ4 + lane], nwt65));
        if (b1 != 0xFF) r1 = f4add(r1, f4add(sT[(70 + b1) * TZ4 + lane], nwt65));
        if (b2 != 0xFF) r2 = f4add(r2, f4add(sT[(70 + b2) * TZ4 + lane], nwt65));
        if (b3 != 0xFF) r3 = f4add(r3, f4add(sT[(70 + b3) * TZ4 + lane], nwt65));

        float4* p = out4 + (size_t)(4 * u) * TZ4 + lane;
        __stcs(p,           r0);
        __stcs(p + TZ4,     r1);
        __stcs(p + 2 * TZ4, r2);
        __stcs(p + 3 * TZ4, r3);
    }
}

extern "C" void kernel_launch(void* const* d_in, const int* in_sizes, int n_in,
                              void* d_out, int out_size) {
    const int*   asym = (const int*)d_in[0];
    const int*   resi = (const int*)d_in[1];
    const int*   entp = (const int*)d_in[2];
    const int*   tokp = (const int*)d_in[3];
    const int*   symp = (const int*)d_in[4];
    const int*   cycp = (const int*)d_in[5];
    const float* W    = (const float*)d_in[6];
    float* out = (float*)d_out;

    cudaFuncSetAttribute(relpos_kernel,
                         cudaFuncAttributeMaxDynamicSharedMemorySize, SMEM_BYTES);

    relpos_kernel<<<2 * LSEQ, 256, SMEM_BYTES>>>(asym, resi, entp, tokp, symp, cycp, W, out);
}